// round 14
// baseline (speedup 1.0000x reference)
#include <cuda_runtime.h>
#include <cuda_bf16.h>
#include <cstdint>

using bf16 = __nv_bfloat16;

// Problem constants
constexpr int cB  = 8;
constexpr int cT  = 512;
constexpr int cD  = 1024;
constexpr int cH  = 16;
constexpr int cDK = 64;
constexpr int cS  = 2 * cT - 1;   // 1023
constexpr int cBH = cB * cH;      // 128

// ---------------------------------------------------------------------------
// Scratch (device globals — no allocation allowed). All bf16 pairs are exact
// hi/lo splits of fp32 values (hi = bf16(v), lo = bf16(v - hi)).
// ---------------------------------------------------------------------------
__device__ bf16  g_xh [4096 * 1024],  g_xl [4096 * 1024];    // x
__device__ bf16  g_Wqh[3072 * 1024],  g_Wql[3072 * 1024];    // Wqkv
__device__ bf16  g_Wph[1024 * 1024],  g_Wpl[1024 * 1024];    // Wpos
__device__ bf16  g_psh[1024 * 1024],  g_psl[1024 * 1024];    // pos (padded)
__device__ bf16  g_Woh[1024 * 1024],  g_Wol[1024 * 1024];    // Wout
__device__ bf16  g_quh[cBH * cT * cDK], g_qul[cBH * cT * cDK];
__device__ bf16  g_qvh[cBH * cT * cDK], g_qvl[cBH * cT * cDK];
__device__ bf16  g_kh [cBH * cT * cDK], g_kl [cBH * cT * cDK];
__device__ bf16  g_vTh[cBH * cDK * cT], g_vTl[cBH * cDK * cT];   // [bh, d, t]
__device__ bf16  g_ph [cH * 1024 * cDK], g_pl [cH * 1024 * cDK]; // [h, s(pad), d]
__device__ float g_bdg[cBH * cT * cT];                           // pre-gathered BD
__device__ bf16  g_wh [cBH * cT * cT], g_wl [cBH * cT * cT];     // softmax weights
__device__ bf16  g_cth[4096 * 1024],  g_ctl[4096 * 1024];        // ctx rows
__device__ float g_w  [cBH * cT * cT];                           // fallback fp32 weights

// ---------------------------------------------------------------------------
// Helpers
// ---------------------------------------------------------------------------
__device__ __forceinline__ void mma16816(float* d, const uint32_t* a,
                                         const uint32_t* b) {
    asm volatile(
        "mma.sync.aligned.m16n8k16.row.col.f32.bf16.bf16.f32 "
        "{%0,%1,%2,%3}, {%4,%5,%6,%7}, {%8,%9}, {%0,%1,%2,%3};"
        : "+f"(d[0]), "+f"(d[1]), "+f"(d[2]), "+f"(d[3])
        : "r"(a[0]), "r"(a[1]), "r"(a[2]), "r"(a[3]), "r"(b[0]), "r"(b[1]));
}
__device__ __forceinline__ void split_store(float v, bf16* hi, bf16* lo, size_t idx) {
    bf16 h = __float2bfloat16_rn(v);
    hi[idx] = h;
    lo[idx] = __float2bfloat16_rn(v - __bfloat162float(h));
}
__device__ __forceinline__ void split_store2(float v0, float v1,
                                             bf16* hi, bf16* lo, size_t idx) {
    bf16 h0 = __float2bfloat16_rn(v0);
    bf16 h1 = __float2bfloat16_rn(v1);
    __nv_bfloat162 hh = __halves2bfloat162(h0, h1);
    *(__nv_bfloat162*)(hi + idx) = hh;
    __nv_bfloat162 ll = __halves2bfloat162(
        __float2bfloat16_rn(v0 - __bfloat162float(h0)),
        __float2bfloat16_rn(v1 - __bfloat162float(h1)));
    *(__nv_bfloat162*)(lo + idx) = ll;
}
__device__ __forceinline__ uint32_t pk2(bf16 a, bf16 b) {
    __nv_bfloat162 t = __halves2bfloat162(a, b);
    return *(uint32_t*)&t;
}
__device__ __forceinline__ void cpasync16(uint32_t s, const void* g, uint32_t sz) {
    asm volatile("cp.async.cg.shared.global [%0], [%1], 16, %2;"
                 :: "r"(s), "l"(g), "r"(sz) : "memory");
}
#define LDM4(r, addr) \
    asm volatile("ldmatrix.sync.aligned.m8n8.x4.shared.b16 {%0,%1,%2,%3}, [%4];" \
        : "=r"((r)[0]), "=r"((r)[1]), "=r"((r)[2]), "=r"((r)[3]) : "r"(addr))

// ---------------------------------------------------------------------------
// Fused fp32 -> bf16 hi/lo splitter for all 5 input tensors.
// ---------------------------------------------------------------------------
__global__ __launch_bounds__(256)
void conv_all(const float* __restrict__ x,   const float* __restrict__ Wq,
              const float* __restrict__ Wp,  const float* __restrict__ ps,
              const float* __restrict__ Wo)
{
    const int t = blockIdx.y;
    const float* src; bf16 *hi, *lo; int n, nreal;
    if      (t == 0) { src = x;  hi = g_xh;  lo = g_xl;  n = 4096 * 1024; nreal = n; }
    else if (t == 1) { src = Wq; hi = g_Wqh; lo = g_Wql; n = 3072 * 1024; nreal = n; }
    else if (t == 2) { src = Wp; hi = g_Wph; lo = g_Wpl; n = 1024 * 1024; nreal = n; }
    else if (t == 3) { src = ps; hi = g_psh; lo = g_psl; n = 1024 * 1024; nreal = cS * 1024; }
    else             { src = Wo; hi = g_Woh; lo = g_Wol; n = 1024 * 1024; nreal = n; }

    const int i0 = (blockIdx.x * 256 + threadIdx.x) * 4;
    if (i0 >= n) return;
    float v[4];
#pragma unroll
    for (int j = 0; j < 4; ++j) {
        const int i = i0 + j;
        v[j] = (i < nreal) ? src[i] : 0.f;
    }
    bf16 h[4], l[4];
#pragma unroll
    for (int j = 0; j < 4; ++j) {
        h[j] = __float2bfloat16_rn(v[j]);
        l[j] = __float2bfloat16_rn(v[j] - __bfloat162float(h[j]));
    }
    *(uint2*)(hi + i0) = make_uint2(pk2(h[0], h[1]), pk2(h[2], h[3]));
    *(uint2*)(lo + i0) = make_uint2(pk2(l[0], l[1]), pk2(l[2], l[3]));
}

// ---------------------------------------------------------------------------
// Universal HMMA GEMM  C = A @ B^T, pre-split bf16 operands, cp.async
// staging + ldmatrix fragment loads. K-chunks of 32 (16 u32, row stride 20).
// Template: MODE epilogue, TN tile width (128/64), PIPE pipeline depth (2/3),
// SINGLE: K=64 fast path (stage both chunks, one wait, one sync).
// No min-blocks clamp — R11/R12 showed the register cap costs more than
// 2-CTA residency buys.
// ---------------------------------------------------------------------------
constexpr uint32_t ARR_U32 = 128 * 20;
constexpr uint32_t ABY     = ARR_U32 * 4;          // 10240 bytes (A arrays)

template <int MODE, int TN = 128, int PIPE = 2, int SINGLE = 0>
__global__ __launch_bounds__(256)
void bmma(const bf16* __restrict__ Ah_, const bf16* __restrict__ Al_,
          const bf16* __restrict__ Bh_, const bf16* __restrict__ Bl_,
          const float* __restrict__ bias, const float* __restrict__ pu,
          const float* __restrict__ pv, const unsigned int* __restrict__ mask,
          float* __restrict__ outf, int K, int NB)
{
    constexpr uint32_t BBY = (uint32_t)TN * 20 * 4;
    constexpr uint32_t BUF = 2 * ABY + 2 * BBY;
    constexpr int NTT = TN / 32;
    constexpr int NP  = TN / 64;

    extern __shared__ uint32_t smem[];
    const uint32_t sbase = (uint32_t)__cvta_generic_to_shared(smem);

    const int tid   = threadIdx.x;
    const int wid   = tid >> 5;
    const int lane  = tid & 31;
    const int group = lane >> 2;
    const int tig   = lane & 3;
    const int wm    = (wid & 1) * 64;
    const int wn    = (wid >> 1) * (TN / 4);
    const int m0    = blockIdx.y * 128;
    const int n0    = (MODE == 2) ? (3 - (int)blockIdx.y + (int)blockIdx.x) * 128
                                  : blockIdx.x * TN;
    const int z     = blockIdx.z;

    const int lane7 = lane & 7;
    const int q     = lane >> 3;
    const int a_ro  = ((q & 1) << 3) + lane7;
    const int a_co  = (q >> 1) << 2;
    const int b_ro  = ((q >> 1) << 3) + lane7;
    const int b_co  = (q & 1) << 2;

    const bf16 *Ah = Ah_, *Al = Al_, *Bh = Bh_, *Bl = Bl_;
    if (MODE == 2) {            // qv @ p^T
        Ah += (size_t)z * cT * cDK;  Al += (size_t)z * cT * cDK;
        Bh += (size_t)(z & 15) * 1024 * cDK;
        Bl += (size_t)(z & 15) * 1024 * cDK;
    } else if (MODE == 3) {     // qu @ k^T
        Ah += (size_t)z * cT * cDK;  Al += (size_t)z * cT * cDK;
        Bh += (size_t)z * cT * cDK;  Bl += (size_t)z * cT * cDK;
    } else if (MODE == 4) {     // w @ vT^T
        Ah += (size_t)z * cT * cT;   Al += (size_t)z * cT * cT;
        Bh += (size_t)z * cDK * cT;  Bl += (size_t)z * cDK * cT;
    }

    float acc[4][NTT][4];
#pragma unroll
    for (int mt = 0; mt < 4; ++mt)
#pragma unroll
        for (int nt = 0; nt < NTT; ++nt)
#pragma unroll
            for (int e = 0; e < 4; ++e) acc[mt][nt][e] = 0.f;

    const int nIter = K / 32;

    auto stage = [&](int it) {
        const int k0 = it * 32;
        const uint32_t bufo = (uint32_t)(it % PIPE) * BUF;
#pragma unroll
        for (int l = 0; l < 2; ++l) {
            const int i  = tid + l * 256;
            const int r  = i >> 2;
            const int c8 = i & 3;
            const uint32_t so = bufo + (uint32_t)(r * 80 + c8 * 16);
            const size_t ga = (size_t)(m0 + r) * K + k0 + c8 * 8;
            cpasync16(sbase + so,       Ah + ga, 16);
            cpasync16(sbase + ABY + so, Al + ga, 16);
            if (r < TN) {
                const bool bok = (n0 + r) < NB;
                const int  rb  = bok ? (n0 + r) : 0;
                const uint32_t sz = bok ? 16u : 0u;
                const size_t gb = (size_t)rb * K + k0 + c8 * 8;
                cpasync16(sbase + 2 * ABY + so, Bh + gb, sz);
                cpasync16(sbase + 2 * ABY + BBY + so, Bl + gb, sz);
            }
        }
        asm volatile("cp.async.commit_group;" ::: "memory");
    };

    auto compute = [&](int it) {
        const uint32_t bo = sbase + (uint32_t)(it % PIPE) * BUF;
#pragma unroll
        for (int ks = 0; ks < 2; ++ks) {
            const int kc = ks * 8;
            uint32_t afh[4][4], afl[4][4], bfh[NTT][2], bfl[NTT][2];
#pragma unroll
            for (int mt = 0; mt < 4; ++mt) {
                const uint32_t ra = bo +
                    (uint32_t)((wm + mt * 16 + a_ro) * 80 + (kc + a_co) * 4);
                LDM4(afh[mt], ra);
                LDM4(afl[mt], ra + ABY);
            }
#pragma unroll
            for (int np = 0; np < NP; ++np) {
                const uint32_t rb = bo + 2 * ABY +
                    (uint32_t)((wn + np * 16 + b_ro) * 80 + (kc + b_co) * 4);
                uint32_t t[4];
                LDM4(t, rb);
                bfh[np * 2][0] = t[0]; bfh[np * 2][1] = t[1];
                bfh[np * 2 + 1][0] = t[2]; bfh[np * 2 + 1][1] = t[3];
                LDM4(t, rb + BBY);
                bfl[np * 2][0] = t[0]; bfl[np * 2][1] = t[1];
                bfl[np * 2 + 1][0] = t[2]; bfl[np * 2 + 1][1] = t[3];
            }
#pragma unroll
            for (int mt = 0; mt < 4; ++mt)
#pragma unroll
                for (int nt = 0; nt < NTT; ++nt) {
                    mma16816(acc[mt][nt], afh[mt], bfh[nt]);
                    mma16816(acc[mt][nt], afh[mt], bfl[nt]);
                    mma16816(acc[mt][nt], afl[mt], bfh[nt]);
                }
        }
    };

    if (SINGLE) {
        // K == 64: both chunks staged at once, one wait, one sync.
        stage(0);
        stage(1);
        asm volatile("cp.async.wait_group 0;" ::: "memory");
        __syncthreads();
        compute(0);
        compute(1);
    } else if (PIPE == 3) {
        // Deep pipeline: wait always targets a chunk staged 2 phases back.
        stage(0);
        stage(1);
        for (int it = 0; it < nIter; ++it) {
            __syncthreads();                  // compute(it-1) done; buf (it+2)%3 free
            if (it + 2 < nIter) {
                stage(it + 2);
                asm volatile("cp.async.wait_group 2;" ::: "memory");
            } else if (it + 1 < nIter) {
                asm volatile("cp.async.wait_group 1;" ::: "memory");
            } else {
                asm volatile("cp.async.wait_group 0;" ::: "memory");
            }
            __syncthreads();                  // chunk it visible
            compute(it);
        }
    } else {
        stage(0);
        for (int it = 0; it < nIter; ++it) {
            __syncthreads();
            if (it + 1 < nIter) {
                stage(it + 1);
                asm volatile("cp.async.wait_group 1;" ::: "memory");
            } else {
                asm volatile("cp.async.wait_group 0;" ::: "memory");
            }
            __syncthreads();
            compute(it);
        }
    }

    // Epilogue: element pairs (e, e+1) are same-row adjacent columns.
#pragma unroll
    for (int mt = 0; mt < 4; ++mt)
#pragma unroll
        for (int nt = 0; nt < NTT; ++nt)
#pragma unroll
            for (int ep = 0; ep < 2; ++ep) {
                const int row = wm + mt * 16 + group + ep * 8;
                const int col = wn + nt * 8 + tig * 2;
                const int m = m0 + row;
                const int n = n0 + col;           // even
                float v0 = acc[mt][nt][ep * 2];
                float v1 = acc[mt][nt][ep * 2 + 1];

                if (MODE == 0) {
                    v0 += bias[n];  v1 += bias[n + 1];
                    const int part = n >> 10;
                    const int nn   = n & 1023;
                    const int hh   = nn >> 6, dd = nn & 63;
                    const int bb   = m >> 9,  tt = m & 511;
                    const int bh   = bb * cH + hh;
                    if (part == 0) {
                        const size_t idx = ((size_t)bh * cT + tt) * cDK + dd;
                        split_store2(v0 + pu[nn], v1 + pu[nn + 1], g_quh, g_qul, idx);
                        split_store2(v0 + pv[nn], v1 + pv[nn + 1], g_qvh, g_qvl, idx);
                    } else if (part == 1) {
                        const size_t idx = ((size_t)bh * cT + tt) * cDK + dd;
                        split_store2(v0, v1, g_kh, g_kl, idx);
                    } else {
                        const size_t i0 = ((size_t)bh * cDK + dd) * cT + tt;
                        split_store(v0, g_vTh, g_vTl, i0);
                        split_store(v1, g_vTh, g_vTl, i0 + cT);
                    }
                } else if (MODE == 1) {
                    if (m < cS) {
                        const int hh = n >> 6, dd = n & 63;
                        split_store2(v0, v1, g_ph, g_pl,
                                     ((size_t)hh * 1024 + m) * cDK + dd);
                    }
                } else if (MODE == 2) {
                    const int s = n + m - (cT - 1);
                    float* dst = &g_bdg[((size_t)z * cT + m) * cT + s];
                    if ((unsigned)s < (unsigned)cT) dst[0] = v0;
                    if ((unsigned)(s + 1) < (unsigned)cT) dst[1] = v1;
                } else if (MODE == 3) {
                    const int bb = z >> 4;
                    const size_t o = ((size_t)z * cT + m) * cT + n;
                    const float2 bd = *(const float2*)&g_bdg[o];
                    const uint2  mk = *(const uint2*)&mask[((size_t)bb * cT + m) * cT + n];
                    float2 r;
                    r.x = mk.x ? (v0 + bd.x) * 0.125f : -100000.0f;
                    r.y = mk.y ? (v1 + bd.y) * 0.125f : -100000.0f;
                    *(float2*)&outf[o] = r;
                } else if (MODE == 4) {
                    const int bb = z >> 4, hh = z & 15;
                    const size_t idx = ((size_t)(bb * cT + m)) * cD + hh * cDK + n;
                    split_store2(v0, v1, g_cth, g_ctl, idx);
                } else {
                    float2 r = make_float2(v0 + bias[n], v1 + bias[n + 1]);
                    *(float2*)&outf[(size_t)m * cD + n] = r;
                }
            }
}

// ---------------------------------------------------------------------------
// Row softmax: fp32 in/out (wptr) + packed bf16 hi/lo weights for ctx GEMM.
// ---------------------------------------------------------------------------
__global__ __launch_bounds__(128)
void softmax_kernel(float* __restrict__ w)
{
    const size_t row = blockIdx.x;
    const int tid = threadIdx.x;
    float* p = w + row * cT + tid * 4;
    const float4 v = *(const float4*)p;

    float m = fmaxf(fmaxf(v.x, v.y), fmaxf(v.z, v.w));
#pragma unroll
    for (int o = 16; o; o >>= 1) m = fmaxf(m, __shfl_xor_sync(0xffffffffu, m, o));

    __shared__ float sm[4], ss[4];
    const int wi = tid >> 5, lane = tid & 31;
    if (lane == 0) sm[wi] = m;
    __syncthreads();
    m = fmaxf(fmaxf(sm[0], sm[1]), fmaxf(sm[2], sm[3]));

    const float e0 = __expf(v.x - m);
    const float e1 = __expf(v.y - m);
    const float e2 = __expf(v.z - m);
    const float e3 = __expf(v.w - m);
    float s = e0 + e1 + e2 + e3;
#pragma unroll
    for (int o = 16; o; o >>= 1) s += __shfl_xor_sync(0xffffffffu, s, o);
    if (lane == 0) ss[wi] = s;
    __syncthreads();
    s = ss[0] + ss[1] + ss[2] + ss[3];

    const float inv = 1.0f / s;
    const float w0 = e0 * inv, w1 = e1 * inv, w2 = e2 * inv, w3 = e3 * inv;
    *(float4*)p = make_float4(w0, w1, w2, w3);

    bf16 h0 = __float2bfloat16_rn(w0), h1 = __float2bfloat16_rn(w1);
    bf16 h2 = __float2bfloat16_rn(w2), h3 = __float2bfloat16_rn(w3);
    const size_t base = row * cT + tid * 4;
    *(uint2*)(g_wh + base) = make_uint2(pk2(h0, h1), pk2(h2, h3));
    *(uint2*)(g_wl + base) = make_uint2(
        pk2(__float2bfloat16_rn(w0 - __bfloat162float(h0)),
            __float2bfloat16_rn(w1 - __bfloat162float(h1))),
        pk2(__float2bfloat16_rn(w2 - __bfloat162float(h2)),
            __float2bfloat16_rn(w3 - __bfloat162float(h3))));
}

// ---------------------------------------------------------------------------
// kernel_launch
// ---------------------------------------------------------------------------
extern "C" void kernel_launch(void* const* d_in, const int* in_sizes, int n_in,
                              void* d_out, int out_size)
{
    const float*        x    = (const float*)d_in[0];
    const unsigned int* mask = (const unsigned int*)d_in[1];
    const float*        pos  = (const float*)d_in[2];
    const float*        Wqkv = (const float*)d_in[3];
    const float*        bqkv = (const float*)d_in[4];
    const float*        Wpos = (const float*)d_in[5];
    const float*        posu = (const float*)d_in[6];
    const float*        posv = (const float*)d_in[7];
    const float*        Wout = (const float*)d_in[8];
    const float*        bout = (const float*)d_in[9];
    float* out = (float*)d_out;

    const int nOut = cB * cT * cD;
    const int nW   = cBH * cT * cT;

    float* wptr;
    if (out_size >= nOut + nW) {
        wptr = out + nOut;
    } else {
        void* p = nullptr;
        cudaGetSymbolAddress(&p, g_w);
        wptr = (float*)p;
    }

    void *pxh, *pxl, *pWqh, *pWql, *pWph, *pWpl, *ppsh, *ppsl, *pWoh, *pWol;
    void *pquh, *pqul, *pqvh, *pqvl, *pkh, *pkl, *pvTh, *pvTl, *pph, *ppl;
    void *pwh, *pwl, *pcth, *pctl;
    cudaGetSymbolAddress(&pxh, g_xh);   cudaGetSymbolAddress(&pxl, g_xl);
    cudaGetSymbolAddress(&pWqh, g_Wqh); cudaGetSymbolAddress(&pWql, g_Wql);
    cudaGetSymbolAddress(&pWph, g_Wph); cudaGetSymbolAddress(&pWpl, g_Wpl);
    cudaGetSymbolAddress(&ppsh, g_psh); cudaGetSymbolAddress(&ppsl, g_psl);
    cudaGetSymbolAddress(&pWoh, g_Woh); cudaGetSymbolAddress(&pWol, g_Wol);
    cudaGetSymbolAddress(&pquh, g_quh); cudaGetSymbolAddress(&pqul, g_qul);
    cudaGetSymbolAddress(&pqvh, g_qvh); cudaGetSymbolAddress(&pqvl, g_qvl);
    cudaGetSymbolAddress(&pkh, g_kh);   cudaGetSymbolAddress(&pkl, g_kl);
    cudaGetSymbolAddress(&pvTh, g_vTh); cudaGetSymbolAddress(&pvTl, g_vTl);
    cudaGetSymbolAddress(&pph, g_ph);   cudaGetSymbolAddress(&ppl, g_pl);
    cudaGetSymbolAddress(&pwh, g_wh);   cudaGetSymbolAddress(&pwl, g_wl);
    cudaGetSymbolAddress(&pcth, g_cth); cudaGetSymbolAddress(&pctl, g_ctl);

    // Dynamic smem: PIPE buffers of (2*ABY + 2*BBY)
    constexpr uint32_t SM_P3  = 3 * (2 * 10240u + 2 * 10240u);   // 122880 (TN=128, PIPE=3)
    constexpr uint32_t SM_P2  = 2 * (2 * 10240u + 2 * 10240u);   // 81920  (TN=128, PIPE=2)
    constexpr uint32_t SM_CTX = 2 * (2 * 10240u + 2 * 5120u);    // 61440  (TN=64,  PIPE=2)

    cudaFuncSetAttribute((bmma<0, 128, 3, 0>), cudaFuncAttributeMaxDynamicSharedMemorySize, SM_P3);
    cudaFuncSetAttribute((bmma<1, 128, 3, 0>), cudaFuncAttributeMaxDynamicSharedMemorySize, SM_P3);
    cudaFuncSetAttribute((bmma<2, 128, 2, 1>), cudaFuncAttributeMaxDynamicSharedMemorySize, SM_P2);
    cudaFuncSetAttribute((bmma<3, 128, 2, 1>), cudaFuncAttributeMaxDynamicSharedMemorySize, SM_P2);
    cudaFuncSetAttribute((bmma<4, 64, 2, 0>),  cudaFuncAttributeMaxDynamicSharedMemorySize, SM_CTX);
    cudaFuncSetAttribute((bmma<5, 128, 3, 0>), cudaFuncAttributeMaxDynamicSharedMemorySize, SM_P3);

    // 0. Fused operand splits (single launch, grid.y = tensor id)
    conv_all<<<dim3(4096, 5), 256>>>(x, Wqkv, Wpos, pos, Wout);

    // 1. QKV projection (+bias, +posu/posv) -> qu/qv/k/vT bf16 splits (PIPE=3)
    bmma<0, 128, 3, 0><<<dim3(24, 32), 256, SM_P3>>>(
        (bf16*)pxh, (bf16*)pxl, (bf16*)pWqh, (bf16*)pWql,
        bqkv, posu, posv, nullptr, nullptr, 1024, 3072);

    // 2. Positional projection -> p bf16 splits (PIPE=3)
    bmma<1, 128, 3, 0><<<dim3(8, 8), 256, SM_P3>>>(
        (bf16*)ppsh, (bf16*)ppsl, (bf16*)pWph, (bf16*)pWpl,
        nullptr, nullptr, nullptr, nullptr, nullptr, 1024, 1024);

    // 3. BD = qv @ p^T, window-skipped, single-shot staging (no reg clamp)
    bmma<2, 128, 2, 1><<<dim3(5, 4, cBH), 256, SM_P2>>>(
        (bf16*)pqvh, (bf16*)pqvl, (bf16*)pph, (bf16*)ppl,
        nullptr, nullptr, nullptr, nullptr, nullptr, 64, 1024);

    // 4. AC = qu @ k^T; scores = (AC + BD)*0.125 masked, single-shot
    bmma<3, 128, 2, 1><<<dim3(4, 4, cBH), 256, SM_P2>>>(
        (bf16*)pquh, (bf16*)pqul, (bf16*)pkh, (bf16*)pkl,
        nullptr, nullptr, nullptr, mask, wptr, 64, 512);

    // 5. Softmax -> fp32 weights (output) + bf16 splits for ctx
    softmax_kernel<<<cBH * cT, 128>>>(wptr);

    // 6. ctx = w @ vT^T (TN=64, 2-stage pipeline, unconstrained regs)
    bmma<4, 64, 2, 0><<<dim3(1, 4, cBH), 256, SM_CTX>>>(
        (bf16*)pwh, (bf16*)pwl, (bf16*)pvTh, (bf16*)pvTl,
        nullptr, nullptr, nullptr, nullptr, nullptr, 512, 64);

    // 7. out = ctx @ Wout^T + bout (PIPE=3)
    bmma<5, 128, 3, 0><<<dim3(8, 32), 256, SM_P3>>>(
        (bf16*)pcth, (bf16*)pctl, (bf16*)pWoh, (bf16*)pWol,
        bout, nullptr, nullptr, nullptr, out, 1024, 1024);
}

// round 15
// speedup vs baseline: 1.1491x; 1.1491x over previous
#include <cuda_runtime.h>
#include <cuda_bf16.h>
#include <cstdint>

using bf16 = __nv_bfloat16;

// Problem constants
constexpr int cB  = 8;
constexpr int cT  = 512;
constexpr int cD  = 1024;
constexpr int cH  = 16;
constexpr int cDK = 64;
constexpr int cS  = 2 * cT - 1;   // 1023
constexpr int cBH = cB * cH;      // 128

// ---------------------------------------------------------------------------
// Scratch (device globals — no allocation allowed). All bf16 pairs are exact
// hi/lo splits of fp32 values (hi = bf16(v), lo = bf16(v - hi)).
// ---------------------------------------------------------------------------
__device__ bf16  g_xh [4096 * 1024],  g_xl [4096 * 1024];    // x
__device__ bf16  g_Wqh[3072 * 1024],  g_Wql[3072 * 1024];    // Wqkv
__device__ bf16  g_Wph[1024 * 1024],  g_Wpl[1024 * 1024];    // Wpos
__device__ bf16  g_psh[1024 * 1024],  g_psl[1024 * 1024];    // pos (padded)
__device__ bf16  g_Woh[1024 * 1024],  g_Wol[1024 * 1024];    // Wout
__device__ bf16  g_quh[cBH * cT * cDK], g_qul[cBH * cT * cDK];
__device__ bf16  g_qvh[cBH * cT * cDK], g_qvl[cBH * cT * cDK];
__device__ bf16  g_kh [cBH * cT * cDK], g_kl [cBH * cT * cDK];
__device__ bf16  g_vTh[cBH * cDK * cT], g_vTl[cBH * cDK * cT];   // [bh, d, t]
__device__ bf16  g_ph [cH * 1024 * cDK], g_pl [cH * 1024 * cDK]; // [h, s(pad), d]
__device__ bf16  g_wh [cBH * cT * cT], g_wl [cBH * cT * cT];     // softmax weights
__device__ bf16  g_cth[4096 * 1024],  g_ctl[4096 * 1024];        // ctx rows
__device__ float g_w  [cBH * cT * cT];                           // fallback fp32 weights

// ---------------------------------------------------------------------------
// Helpers
// ---------------------------------------------------------------------------
__device__ __forceinline__ void mma16816(float* d, const uint32_t* a,
                                         const uint32_t* b) {
    asm volatile(
        "mma.sync.aligned.m16n8k16.row.col.f32.bf16.bf16.f32 "
        "{%0,%1,%2,%3}, {%4,%5,%6,%7}, {%8,%9}, {%0,%1,%2,%3};"
        : "+f"(d[0]), "+f"(d[1]), "+f"(d[2]), "+f"(d[3])
        : "r"(a[0]), "r"(a[1]), "r"(a[2]), "r"(a[3]), "r"(b[0]), "r"(b[1]));
}
__device__ __forceinline__ void split_store(float v, bf16* hi, bf16* lo, size_t idx) {
    bf16 h = __float2bfloat16_rn(v);
    hi[idx] = h;
    lo[idx] = __float2bfloat16_rn(v - __bfloat162float(h));
}
__device__ __forceinline__ void split_store2(float v0, float v1,
                                             bf16* hi, bf16* lo, size_t idx) {
    bf16 h0 = __float2bfloat16_rn(v0);
    bf16 h1 = __float2bfloat16_rn(v1);
    __nv_bfloat162 hh = __halves2bfloat162(h0, h1);
    *(__nv_bfloat162*)(hi + idx) = hh;
    __nv_bfloat162 ll = __halves2bfloat162(
        __float2bfloat16_rn(v0 - __bfloat162float(h0)),
        __float2bfloat16_rn(v1 - __bfloat162float(h1)));
    *(__nv_bfloat162*)(lo + idx) = ll;
}
__device__ __forceinline__ uint32_t pk2(bf16 a, bf16 b) {
    __nv_bfloat162 t = __halves2bfloat162(a, b);
    return *(uint32_t*)&t;
}
__device__ __forceinline__ void cpasync16(uint32_t s, const void* g, uint32_t sz) {
    asm volatile("cp.async.cg.shared.global [%0], [%1], 16, %2;"
                 :: "r"(s), "l"(g), "r"(sz) : "memory");
}
#define LDM4(r, addr) \
    asm volatile("ldmatrix.sync.aligned.m8n8.x4.shared.b16 {%0,%1,%2,%3}, [%4];" \
        : "=r"((r)[0]), "=r"((r)[1]), "=r"((r)[2]), "=r"((r)[3]) : "r"(addr))

// ---------------------------------------------------------------------------
// Fused fp32 -> bf16 hi/lo splitter for all 5 input tensors.
// ---------------------------------------------------------------------------
__global__ __launch_bounds__(256)
void conv_all(const float* __restrict__ x,   const float* __restrict__ Wq,
              const float* __restrict__ Wp,  const float* __restrict__ ps,
              const float* __restrict__ Wo)
{
    const int t = blockIdx.y;
    const float* src; bf16 *hi, *lo; int n, nreal;
    if      (t == 0) { src = x;  hi = g_xh;  lo = g_xl;  n = 4096 * 1024; nreal = n; }
    else if (t == 1) { src = Wq; hi = g_Wqh; lo = g_Wql; n = 3072 * 1024; nreal = n; }
    else if (t == 2) { src = Wp; hi = g_Wph; lo = g_Wpl; n = 1024 * 1024; nreal = n; }
    else if (t == 3) { src = ps; hi = g_psh; lo = g_psl; n = 1024 * 1024; nreal = cS * 1024; }
    else             { src = Wo; hi = g_Woh; lo = g_Wol; n = 1024 * 1024; nreal = n; }

    const int i0 = (blockIdx.x * 256 + threadIdx.x) * 4;
    if (i0 >= n) return;
    float v[4];
#pragma unroll
    for (int j = 0; j < 4; ++j) {
        const int i = i0 + j;
        v[j] = (i < nreal) ? src[i] : 0.f;
    }
    bf16 h[4], l[4];
#pragma unroll
    for (int j = 0; j < 4; ++j) {
        h[j] = __float2bfloat16_rn(v[j]);
        l[j] = __float2bfloat16_rn(v[j] - __bfloat162float(h[j]));
    }
    *(uint2*)(hi + i0) = make_uint2(pk2(h[0], h[1]), pk2(h[2], h[3]));
    *(uint2*)(lo + i0) = make_uint2(pk2(l[0], l[1]), pk2(l[2], l[3]));
}

// ---------------------------------------------------------------------------
// Universal HMMA GEMM  C = A @ B^T (R10-proven form: 2-stage cp.async
// pipeline + ldmatrix, K-chunks of 32, no launch-bounds clamp).
// MODE: 0 QKV scatter, 1 POS scatter, 4 CTX split-store, 5 OUT (+bias).
// ---------------------------------------------------------------------------
constexpr uint32_t ARR_U32 = 128 * 20;
constexpr uint32_t ABY     = ARR_U32 * 4;          // 10240 bytes

template <int MODE, int TN = 128>
__global__ __launch_bounds__(256)
void bmma(const bf16* __restrict__ Ah_, const bf16* __restrict__ Al_,
          const bf16* __restrict__ Bh_, const bf16* __restrict__ Bl_,
          const float* __restrict__ bias, const float* __restrict__ pu,
          const float* __restrict__ pv, float* __restrict__ outf,
          int K, int NB)
{
    constexpr uint32_t BBY = (uint32_t)TN * 20 * 4;
    constexpr uint32_t BUF = 2 * ABY + 2 * BBY;
    constexpr int NTT = TN / 32;
    constexpr int NP  = TN / 64;

    extern __shared__ uint32_t smem[];
    const uint32_t sbase = (uint32_t)__cvta_generic_to_shared(smem);

    const int tid   = threadIdx.x;
    const int wid   = tid >> 5;
    const int lane  = tid & 31;
    const int group = lane >> 2;
    const int tig   = lane & 3;
    const int wm    = (wid & 1) * 64;
    const int wn    = (wid >> 1) * (TN / 4);
    const int m0    = blockIdx.y * 128;
    const int n0    = blockIdx.x * TN;
    const int z     = blockIdx.z;

    const int lane7 = lane & 7;
    const int q     = lane >> 3;
    const int a_ro  = ((q & 1) << 3) + lane7;
    const int a_co  = (q >> 1) << 2;
    const int b_ro  = ((q >> 1) << 3) + lane7;
    const int b_co  = (q & 1) << 2;

    const bf16 *Ah = Ah_, *Al = Al_, *Bh = Bh_, *Bl = Bl_;
    if (MODE == 4) {            // w @ vT^T
        Ah += (size_t)z * cT * cT;   Al += (size_t)z * cT * cT;
        Bh += (size_t)z * cDK * cT;  Bl += (size_t)z * cDK * cT;
    }

    float acc[4][NTT][4];
#pragma unroll
    for (int mt = 0; mt < 4; ++mt)
#pragma unroll
        for (int nt = 0; nt < NTT; ++nt)
#pragma unroll
            for (int e = 0; e < 4; ++e) acc[mt][nt][e] = 0.f;

    const int nIter = K / 32;

    auto stage = [&](int it) {
        const int k0 = it * 32;
        const uint32_t bufo = (uint32_t)(it & 1) * BUF;
#pragma unroll
        for (int l = 0; l < 2; ++l) {
            const int i  = tid + l * 256;
            const int r  = i >> 2;
            const int c8 = i & 3;
            const uint32_t so = bufo + (uint32_t)(r * 80 + c8 * 16);
            const size_t ga = (size_t)(m0 + r) * K + k0 + c8 * 8;
            cpasync16(sbase + so,       Ah + ga, 16);
            cpasync16(sbase + ABY + so, Al + ga, 16);
            if (r < TN) {
                const bool bok = (n0 + r) < NB;
                const int  rb  = bok ? (n0 + r) : 0;
                const uint32_t sz = bok ? 16u : 0u;
                const size_t gb = (size_t)rb * K + k0 + c8 * 8;
                cpasync16(sbase + 2 * ABY + so, Bh + gb, sz);
                cpasync16(sbase + 2 * ABY + BBY + so, Bl + gb, sz);
            }
        }
        asm volatile("cp.async.commit_group;" ::: "memory");
    };

    stage(0);
    for (int it = 0; it < nIter; ++it) {
        __syncthreads();
        if (it + 1 < nIter) {
            stage(it + 1);
            asm volatile("cp.async.wait_group 1;" ::: "memory");
        } else {
            asm volatile("cp.async.wait_group 0;" ::: "memory");
        }
        __syncthreads();

        const uint32_t bo = sbase + (uint32_t)(it & 1) * BUF;
#pragma unroll
        for (int ks = 0; ks < 2; ++ks) {
            const int kc = ks * 8;
            uint32_t afh[4][4], afl[4][4], bfh[NTT][2], bfl[NTT][2];
#pragma unroll
            for (int mt = 0; mt < 4; ++mt) {
                const uint32_t ra = bo +
                    (uint32_t)((wm + mt * 16 + a_ro) * 80 + (kc + a_co) * 4);
                LDM4(afh[mt], ra);
                LDM4(afl[mt], ra + ABY);
            }
#pragma unroll
            for (int np = 0; np < NP; ++np) {
                const uint32_t rb = bo + 2 * ABY +
                    (uint32_t)((wn + np * 16 + b_ro) * 80 + (kc + b_co) * 4);
                uint32_t t[4];
                LDM4(t, rb);
                bfh[np * 2][0] = t[0]; bfh[np * 2][1] = t[1];
                bfh[np * 2 + 1][0] = t[2]; bfh[np * 2 + 1][1] = t[3];
                LDM4(t, rb + BBY);
                bfl[np * 2][0] = t[0]; bfl[np * 2][1] = t[1];
                bfl[np * 2 + 1][0] = t[2]; bfl[np * 2 + 1][1] = t[3];
            }
#pragma unroll
            for (int mt = 0; mt < 4; ++mt)
#pragma unroll
                for (int nt = 0; nt < NTT; ++nt) {
                    mma16816(acc[mt][nt], afh[mt], bfh[nt]);
                    mma16816(acc[mt][nt], afh[mt], bfl[nt]);
                    mma16816(acc[mt][nt], afl[mt], bfh[nt]);
                }
        }
    }

    // Epilogue: element pairs (e, e+1) are same-row adjacent columns.
#pragma unroll
    for (int mt = 0; mt < 4; ++mt)
#pragma unroll
        for (int nt = 0; nt < NTT; ++nt)
#pragma unroll
            for (int ep = 0; ep < 2; ++ep) {
                const int row = wm + mt * 16 + group + ep * 8;
                const int col = wn + nt * 8 + tig * 2;
                const int m = m0 + row;
                const int n = n0 + col;           // even
                float v0 = acc[mt][nt][ep * 2];
                float v1 = acc[mt][nt][ep * 2 + 1];

                if (MODE == 0) {
                    v0 += bias[n];  v1 += bias[n + 1];
                    const int part = n >> 10;
                    const int nn   = n & 1023;
                    const int hh   = nn >> 6, dd = nn & 63;
                    const int bb   = m >> 9,  tt = m & 511;
                    const int bh   = bb * cH + hh;
                    if (part == 0) {
                        const size_t idx = ((size_t)bh * cT + tt) * cDK + dd;
                        split_store2(v0 + pu[nn], v1 + pu[nn + 1], g_quh, g_qul, idx);
                        split_store2(v0 + pv[nn], v1 + pv[nn + 1], g_qvh, g_qvl, idx);
                    } else if (part == 1) {
                        const size_t idx = ((size_t)bh * cT + tt) * cDK + dd;
                        split_store2(v0, v1, g_kh, g_kl, idx);
                    } else {
                        const size_t i0 = ((size_t)bh * cDK + dd) * cT + tt;
                        split_store(v0, g_vTh, g_vTl, i0);
                        split_store(v1, g_vTh, g_vTl, i0 + cT);
                    }
                } else if (MODE == 1) {
                    if (m < cS) {
                        const int hh = n >> 6, dd = n & 63;
                        split_store2(v0, v1, g_ph, g_pl,
                                     ((size_t)hh * 1024 + m) * cDK + dd);
                    }
                } else if (MODE == 4) {
                    const int bb = z >> 4, hh = z & 15;
                    const size_t idx = ((size_t)(bb * cT + m)) * cD + hh * cDK + n;
                    split_store2(v0, v1, g_cth, g_ctl, idx);
                } else {
                    float2 r = make_float2(v0 + bias[n], v1 + bias[n + 1]);
                    *(float2*)&outf[(size_t)m * cD + n] = r;
                }
            }
}

// ---------------------------------------------------------------------------
// Fused BD+AC scores kernel. One CTA = output tile (m0, n0) of (z).
// Phase 1: bd0 = qv @ p[jbase..+128)^T        -> smem fp32
// Phase 2: bd1 = qv @ p[jbase+128..+256)^T    -> smem fp32 (B-only restage)
// Phase 3: ac  = qu @ k^T                     -> registers
// Epilogue: score = (ac + bd_smem[row][col-row+127]) * 0.125, masked.
// jbase = n0 - m0 + 384; all p rows accessed lie in [0, 1023).
// Smem: bd 128 x 260 fp32 (133120 B) + 2 chunk staging buffers (81920 B).
// ---------------------------------------------------------------------------
constexpr uint32_t FS_BDS   = 260;                       // bd row stride (floats)
constexpr uint32_t FS_BDB   = 128u * FS_BDS * 4u;        // 133120
constexpr uint32_t FS_STG   = FS_BDB;                    // staging base offset
constexpr uint32_t FS_BUF   = 4 * ABY;                   // 40960 per chunk
constexpr uint32_t FS_SMEM  = FS_BDB + 2 * FS_BUF;       // 215040

__global__ __launch_bounds__(256)
void fused_scores(const bf16* __restrict__ quh, const bf16* __restrict__ qul,
                  const bf16* __restrict__ qvh, const bf16* __restrict__ qvl,
                  const bf16* __restrict__ kh,  const bf16* __restrict__ kl,
                  const bf16* __restrict__ ph,  const bf16* __restrict__ pl,
                  const unsigned int* __restrict__ mask, float* __restrict__ outf)
{
    extern __shared__ uint32_t smem[];
    const uint32_t sbase = (uint32_t)__cvta_generic_to_shared(smem);
    float* bd = (float*)smem;

    const int tid   = threadIdx.x;
    const int wid   = tid >> 5;
    const int lane  = tid & 31;
    const int group = lane >> 2;
    const int tig   = lane & 3;
    const int wm    = (wid & 1) * 64;
    const int wn    = (wid >> 1) * 32;
    const int m0    = blockIdx.y * 128;
    const int n0    = blockIdx.x * 128;
    const int z     = blockIdx.z;
    const int h     = z & 15;
    const int jbase = n0 - m0 + 384;

    const int lane7 = lane & 7;
    const int q     = lane >> 3;
    const int a_ro  = ((q & 1) << 3) + lane7;
    const int a_co  = (q >> 1) << 2;
    const int b_ro  = ((q >> 1) << 3) + lane7;
    const int b_co  = (q & 1) << 2;

    // Fully-offset operand bases (rows x 64, row-major bf16)
    const bf16* Aqvh = qvh + ((size_t)z * cT + m0) * cDK;
    const bf16* Aqvl = qvl + ((size_t)z * cT + m0) * cDK;
    const bf16* Aquh = quh + ((size_t)z * cT + m0) * cDK;
    const bf16* Aqul = qul + ((size_t)z * cT + m0) * cDK;
    const bf16* Bkh  = kh  + ((size_t)z * cT + n0) * cDK;
    const bf16* Bkl  = kl  + ((size_t)z * cT + n0) * cDK;
    const bf16* Bp0h = ph + ((size_t)h * 1024 + jbase) * cDK;
    const bf16* Bp0l = pl + ((size_t)h * 1024 + jbase) * cDK;
    const bf16* Bp1h = Bp0h + 128 * cDK;
    const bf16* Bp1l = Bp0l + 128 * cDK;

    // Stage both K-chunks (k0 = 0, 32) of A and/or B into the 2 chunk buffers.
    auto stageAB = [&](const bf16* Ah, const bf16* Al,
                       const bf16* Bh, const bf16* Bl, bool doA) {
#pragma unroll
        for (int ch = 0; ch < 2; ++ch) {
            const int k0 = ch * 32;
            const uint32_t bufo = FS_STG + (uint32_t)ch * FS_BUF;
#pragma unroll
            for (int l = 0; l < 2; ++l) {
                const int i  = tid + l * 256;
                const int r  = i >> 2;
                const int c8 = i & 3;
                const uint32_t so = bufo + (uint32_t)(r * 80 + c8 * 16);
                const size_t g = (size_t)r * cDK + k0 + c8 * 8;
                if (doA) {
                    cpasync16(sbase + so,       Ah + g, 16);
                    cpasync16(sbase + ABY + so, Al + g, 16);
                }
                cpasync16(sbase + 2 * ABY + so, Bh + g, 16);
                cpasync16(sbase + 3 * ABY + so, Bl + g, 16);
            }
        }
        asm volatile("cp.async.commit_group;" ::: "memory");
        asm volatile("cp.async.wait_group 0;" ::: "memory");
    };

    float acc[4][4][4];
    auto zeroAcc = [&]() {
#pragma unroll
        for (int mt = 0; mt < 4; ++mt)
#pragma unroll
            for (int nt = 0; nt < 4; ++nt)
#pragma unroll
                for (int e = 0; e < 4; ++e) acc[mt][nt][e] = 0.f;
    };

    // GEMM over the 2 staged chunks (same hh/hl/lh order as bmma).
    auto computeAcc = [&]() {
#pragma unroll
        for (int ch = 0; ch < 2; ++ch) {
            const uint32_t bo = sbase + FS_STG + (uint32_t)ch * FS_BUF;
#pragma unroll
            for (int ks = 0; ks < 2; ++ks) {
                const int kc = ks * 8;
                uint32_t afh[4][4], afl[4][4], bfh[4][2], bfl[4][2];
#pragma unroll
                for (int mt = 0; mt < 4; ++mt) {
                    const uint32_t ra = bo +
                        (uint32_t)((wm + mt * 16 + a_ro) * 80 + (kc + a_co) * 4);
                    LDM4(afh[mt], ra);
                    LDM4(afl[mt], ra + ABY);
                }
#pragma unroll
                for (int np = 0; np < 2; ++np) {
                    const uint32_t rb = bo + 2 * ABY +
                        (uint32_t)((wn + np * 16 + b_ro) * 80 + (kc + b_co) * 4);
                    uint32_t t[4];
                    LDM4(t, rb);
                    bfh[np * 2][0] = t[0]; bfh[np * 2][1] = t[1];
                    bfh[np * 2 + 1][0] = t[2]; bfh[np * 2 + 1][1] = t[3];
                    LDM4(t, rb + ABY);
                    bfl[np * 2][0] = t[0]; bfl[np * 2][1] = t[1];
                    bfl[np * 2 + 1][0] = t[2]; bfl[np * 2 + 1][1] = t[3];
                }
#pragma unroll
                for (int mt = 0; mt < 4; ++mt)
#pragma unroll
                    for (int nt = 0; nt < 4; ++nt) {
                        mma16816(acc[mt][nt], afh[mt], bfh[nt]);
                        mma16816(acc[mt][nt], afh[mt], bfl[nt]);
                        mma16816(acc[mt][nt], afl[mt], bfh[nt]);
                    }
            }
        }
    };

    auto dumpBD = [&](int toff) {
#pragma unroll
        for (int mt = 0; mt < 4; ++mt)
#pragma unroll
            for (int nt = 0; nt < 4; ++nt)
#pragma unroll
                for (int ep = 0; ep < 2; ++ep) {
                    const int row = wm + mt * 16 + group + ep * 8;
                    const int col = wn + nt * 8 + tig * 2;
                    bd[row * FS_BDS + toff + col]     = acc[mt][nt][ep * 2];
                    bd[row * FS_BDS + toff + col + 1] = acc[mt][nt][ep * 2 + 1];
                }
    };

    // Phase 1: bd0
    zeroAcc();
    stageAB(Aqvh, Aqvl, Bp0h, Bp0l, true);
    __syncthreads();
    computeAcc();
    dumpBD(0);
    __syncthreads();          // phase-1 smem reads + bd0 writes done

    // Phase 2: bd1 (A already staged)
    zeroAcc();
    stageAB(nullptr, nullptr, Bp1h, Bp1l, false);
    __syncthreads();
    computeAcc();
    dumpBD(128);
    __syncthreads();          // bd complete and visible

    // Phase 3: ac
    zeroAcc();
    stageAB(Aquh, Aqul, Bkh, Bkl, true);
    __syncthreads();
    computeAcc();

    // Epilogue: score = (ac + bd[row][col - row + 127]) * 0.125, masked
    const int bb = z >> 4;
#pragma unroll
    for (int mt = 0; mt < 4; ++mt)
#pragma unroll
        for (int nt = 0; nt < 4; ++nt)
#pragma unroll
            for (int ep = 0; ep < 2; ++ep) {
                const int row = wm + mt * 16 + group + ep * 8;
                const int col = wn + nt * 8 + tig * 2;
                const int m = m0 + row;
                const int n = n0 + col;
                const int jl = col - row + 127;            // 0..254
                const float b0 = bd[row * FS_BDS + jl];
                const float b1 = bd[row * FS_BDS + jl + 1];
                const uint2 mk = *(const uint2*)&mask[((size_t)bb * cT + m) * cT + n];
                float2 r;
                r.x = mk.x ? (acc[mt][nt][ep * 2]     + b0) * 0.125f : -100000.0f;
                r.y = mk.y ? (acc[mt][nt][ep * 2 + 1] + b1) * 0.125f : -100000.0f;
                *(float2*)&outf[((size_t)z * cT + m) * cT + n] = r;
            }
}

// ---------------------------------------------------------------------------
// Row softmax: fp32 in/out (wptr) + packed bf16 hi/lo weights for ctx GEMM.
// ---------------------------------------------------------------------------
__global__ __launch_bounds__(128)
void softmax_kernel(float* __restrict__ w)
{
    const size_t row = blockIdx.x;
    const int tid = threadIdx.x;
    float* p = w + row * cT + tid * 4;
    const float4 v = *(const float4*)p;

    float m = fmaxf(fmaxf(v.x, v.y), fmaxf(v.z, v.w));
#pragma unroll
    for (int o = 16; o; o >>= 1) m = fmaxf(m, __shfl_xor_sync(0xffffffffu, m, o));

    __shared__ float sm[4], ss[4];
    const int wi = tid >> 5, lane = tid & 31;
    if (lane == 0) sm[wi] = m;
    __syncthreads();
    m = fmaxf(fmaxf(sm[0], sm[1]), fmaxf(sm[2], sm[3]));

    const float e0 = __expf(v.x - m);
    const float e1 = __expf(v.y - m);
    const float e2 = __expf(v.z - m);
    const float e3 = __expf(v.w - m);
    float s = e0 + e1 + e2 + e3;
#pragma unroll
    for (int o = 16; o; o >>= 1) s += __shfl_xor_sync(0xffffffffu, s, o);
    if (lane == 0) ss[wi] = s;
    __syncthreads();
    s = ss[0] + ss[1] + ss[2] + ss[3];

    const float inv = 1.0f / s;
    const float w0 = e0 * inv, w1 = e1 * inv, w2 = e2 * inv, w3 = e3 * inv;
    *(float4*)p = make_float4(w0, w1, w2, w3);

    bf16 h0 = __float2bfloat16_rn(w0), h1 = __float2bfloat16_rn(w1);
    bf16 h2 = __float2bfloat16_rn(w2), h3 = __float2bfloat16_rn(w3);
    const size_t base = row * cT + tid * 4;
    *(uint2*)(g_wh + base) = make_uint2(pk2(h0, h1), pk2(h2, h3));
    *(uint2*)(g_wl + base) = make_uint2(
        pk2(__float2bfloat16_rn(w0 - __bfloat162float(h0)),
            __float2bfloat16_rn(w1 - __bfloat162float(h1))),
        pk2(__float2bfloat16_rn(w2 - __bfloat162float(h2)),
            __float2bfloat16_rn(w3 - __bfloat162float(h3))));
}

// ---------------------------------------------------------------------------
// kernel_launch
// ---------------------------------------------------------------------------
extern "C" void kernel_launch(void* const* d_in, const int* in_sizes, int n_in,
                              void* d_out, int out_size)
{
    const float*        x    = (const float*)d_in[0];
    const unsigned int* mask = (const unsigned int*)d_in[1];
    const float*        pos  = (const float*)d_in[2];
    const float*        Wqkv = (const float*)d_in[3];
    const float*        bqkv = (const float*)d_in[4];
    const float*        Wpos = (const float*)d_in[5];
    const float*        posu = (const float*)d_in[6];
    const float*        posv = (const float*)d_in[7];
    const float*        Wout = (const float*)d_in[8];
    const float*        bout = (const float*)d_in[9];
    float* out = (float*)d_out;

    const int nOut = cB * cT * cD;
    const int nW   = cBH * cT * cT;

    float* wptr;
    if (out_size >= nOut + nW) {
        wptr = out + nOut;
    } else {
        void* p = nullptr;
        cudaGetSymbolAddress(&p, g_w);
        wptr = (float*)p;
    }

    void *pxh, *pxl, *pWqh, *pWql, *pWph, *pWpl, *ppsh, *ppsl, *pWoh, *pWol;
    void *pquh, *pqul, *pqvh, *pqvl, *pkh, *pkl, *pvTh, *pvTl, *pph, *ppl;
    void *pwh, *pwl, *pcth, *pctl;
    cudaGetSymbolAddress(&pxh, g_xh);   cudaGetSymbolAddress(&pxl, g_xl);
    cudaGetSymbolAddress(&pWqh, g_Wqh); cudaGetSymbolAddress(&pWql, g_Wql);
    cudaGetSymbolAddress(&pWph, g_Wph); cudaGetSymbolAddress(&pWpl, g_Wpl);
    cudaGetSymbolAddress(&ppsh, g_psh); cudaGetSymbolAddress(&ppsl, g_psl);
    cudaGetSymbolAddress(&pWoh, g_Woh); cudaGetSymbolAddress(&pWol, g_Wol);
    cudaGetSymbolAddress(&pquh, g_quh); cudaGetSymbolAddress(&pqul, g_qul);
    cudaGetSymbolAddress(&pqvh, g_qvh); cudaGetSymbolAddress(&pqvl, g_qvl);
    cudaGetSymbolAddress(&pkh, g_kh);   cudaGetSymbolAddress(&pkl, g_kl);
    cudaGetSymbolAddress(&pvTh, g_vTh); cudaGetSymbolAddress(&pvTl, g_vTl);
    cudaGetSymbolAddress(&pph, g_ph);   cudaGetSymbolAddress(&ppl, g_pl);
    cudaGetSymbolAddress(&pwh, g_wh);   cudaGetSymbolAddress(&pwl, g_wl);
    cudaGetSymbolAddress(&pcth, g_cth); cudaGetSymbolAddress(&pctl, g_ctl);

    constexpr uint32_t SM_P2  = 2 * (2 * 10240u + 2 * 10240u);   // 81920 (TN=128)
    constexpr uint32_t SM_CTX = 2 * (2 * 10240u + 2 * 5120u);    // 61440 (TN=64)

    cudaFuncSetAttribute((bmma<0, 128>), cudaFuncAttributeMaxDynamicSharedMemorySize, SM_P2);
    cudaFuncSetAttribute((bmma<1, 128>), cudaFuncAttributeMaxDynamicSharedMemorySize, SM_P2);
    cudaFuncSetAttribute((bmma<4, 64>),  cudaFuncAttributeMaxDynamicSharedMemorySize, SM_CTX);
    cudaFuncSetAttribute((bmma<5, 128>), cudaFuncAttributeMaxDynamicSharedMemorySize, SM_P2);
    cudaFuncSetAttribute(fused_scores,   cudaFuncAttributeMaxDynamicSharedMemorySize, FS_SMEM);

    // 0. Fused operand splits
    conv_all<<<dim3(4096, 5), 256>>>(x, Wqkv, Wpos, pos, Wout);

    // 1. QKV projection (+bias, +posu/posv) -> qu/qv/k/vT bf16 splits
    bmma<0, 128><<<dim3(24, 32), 256, SM_P2>>>(
        (bf16*)pxh, (bf16*)pxl, (bf16*)pWqh, (bf16*)pWql,
        bqkv, posu, posv, nullptr, 1024, 3072);

    // 2. Positional projection -> p bf16 splits
    bmma<1, 128><<<dim3(8, 8), 256, SM_P2>>>(
        (bf16*)ppsh, (bf16*)ppsl, (bf16*)pWph, (bf16*)pWpl,
        nullptr, nullptr, nullptr, nullptr, 1024, 1024);

    // 3. Fused BD+AC scores -> wptr (replaces bd kernel + g_bdg roundtrip)
    fused_scores<<<dim3(4, 4, cBH), 256, FS_SMEM>>>(
        (bf16*)pquh, (bf16*)pqul, (bf16*)pqvh, (bf16*)pqvl,
        (bf16*)pkh, (bf16*)pkl, (bf16*)pph, (bf16*)ppl, mask, wptr);

    // 4. Softmax -> fp32 weights (output) + bf16 splits for ctx
    softmax_kernel<<<cBH * cT, 128>>>(wptr);

    // 5. ctx = w @ vT^T (TN=64)
    bmma<4, 64><<<dim3(1, 4, cBH), 256, SM_CTX>>>(
        (bf16*)pwh, (bf16*)pwl, (bf16*)pvTh, (bf16*)pvTl,
        nullptr, nullptr, nullptr, nullptr, 512, 64);

    // 6. out = ctx @ Wout^T + bout
    bmma<5, 128><<<dim3(8, 32), 256, SM_P2>>>(
        (bf16*)pcth, (bf16*)pctl, (bf16*)pWoh, (bf16*)pWol,
        bout, nullptr, nullptr, out, 1024, 1024);
}